// round 9
// baseline (speedup 1.0000x reference)
#include <cuda_runtime.h>
#include <math.h>
#include <stdint.h>

#define NIMG 8
#define CIN 256
#define HW 4096
#define NA 9
#define APIMG 36864
#define NPRE 6000
#define NPOST 300
#define KDIM 2304
#define NWORDS 94
#define NKC 288           // number of k8 chunks

#define OFF_LOC   0
#define OFF_SCORE 1179648
#define OFF_ROIS  1769472
#define OFF_RIDX  1779072
#define OFF_ANCH  1781472

// smem (float indices)
#define AROW 136          // A row stride (136 mod 32 = 8 -> conflict-free frags)
#define APL 1104          // A plane stride (8*138? no: 8*AROW=1088, pad to 1104, mod32=16)
#define BROW 72           // B row stride (mod 32 = 8)
#define BPL 576           // B plane stride (8*72)
#define BOFF3 3312        // 3*APL
#define STG_F 5040        // 3*APL + 3*BPL
#define DSMEM_BYTES (2 * STG_F * 4)   // 40320 B

// ---------------- static device scratch ----------------
__device__ float g_x0[NIMG * HW * CIN];      // NHWC tf32 chunk0
__device__ float g_x1[NIMG * HW * CIN];      // chunk1
__device__ float g_x2[NIMG * HW * CIN];      // chunk2
__device__ float g_w0[KDIM * 256];           // k-major [k][oc] chunk0
__device__ float g_w1[KDIM * 256];
__device__ float g_w2[KDIM * 256];
__device__ float g_h[NIMG * CIN * HW];       // conv out NCHW
__device__ float g_boxes[NIMG * APIMG * 4];
__device__ unsigned g_key[NIMG * APIMG];
__device__ float g_top[NIMG * NPRE * 4];
__device__ unsigned long long g_mask[(size_t)NIMG * NPRE * NWORDS];

// ---------------- helpers ----------------
__device__ __forceinline__ uint32_t smem_u32(const void* p) {
    uint32_t a;
    asm("{ .reg .u64 t; cvta.to.shared.u64 t, %1; cvt.u32.u64 %0, t; }" : "=r"(a) : "l"(p));
    return a;
}
__device__ __forceinline__ void cp16(uint32_t dst, const void* src) {
    asm volatile("cp.async.cg.shared.global [%0], [%1], 16;" :: "r"(dst), "l"(src) : "memory");
}
__device__ __forceinline__ void cp_commit() { asm volatile("cp.async.commit_group;" ::: "memory"); }
__device__ __forceinline__ void cp_wait0() { asm volatile("cp.async.wait_group 0;" ::: "memory"); }
__device__ __forceinline__ float tf32_rn(float v) {
    uint32_t u = __float_as_uint(v), h;
    asm("cvt.rna.tf32.f32 %0, %1;" : "=r"(h) : "r"(u));
    return __uint_as_float(h);
}
__device__ __forceinline__ void mma8(float c[4], const float a[4], float b0, float b1) {
    const uint32_t* A = reinterpret_cast<const uint32_t*>(a);
    asm volatile(
        "mma.sync.aligned.m16n8k8.row.col.f32.tf32.tf32.f32 "
        "{%0,%1,%2,%3}, {%4,%5,%6,%7}, {%8,%9}, {%0,%1,%2,%3};"
        : "+f"(c[0]), "+f"(c[1]), "+f"(c[2]), "+f"(c[3])
        : "r"(A[0]), "r"(A[1]), "r"(A[2]), "r"(A[3]),
          "r"(__float_as_uint(b0)), "r"(__float_as_uint(b1)));
}
__device__ __forceinline__ float read_dim(const void* p) {
    int v = *(const int*)p;
    if (v > 0 && v < 1048576) return (float)v;
    long long l = *(const long long*)p;
    if (l > 0 && l < 1048576) return (float)l;
    return *(const float*)p;
}

// ---------------- K0a: x NCHW -> NHWC 3-way tf32 split ----------------
__global__ void k_xsplit(const float* __restrict__ x) {
    __shared__ float t[32][33];
    int n = blockIdx.z;
    int p0 = blockIdx.x * 32;
    int c0 = blockIdx.y * 32;
    int tx = threadIdx.x, ty = threadIdx.y;
#pragma unroll
    for (int i = 0; i < 4; i++)
        t[tx][ty + i * 8] = x[(((size_t)n * 256 + c0 + ty + i * 8) << 12) + p0 + tx];
    __syncthreads();
#pragma unroll
    for (int i = 0; i < 4; i++) {
        int p = p0 + ty + i * 8;
        float v = t[ty + i * 8][tx];
        float h0 = tf32_rn(v);
        float r = v - h0;
        float h1 = tf32_rn(r);
        float h2 = tf32_rn(r - h1);
        size_t idx = ((((size_t)n << 12) + p) << 8) + c0 + tx;
        g_x0[idx] = h0;
        g_x1[idx] = h1;
        g_x2[idx] = h2;
    }
}

// ---------------- K0b: weights -> k-major 3-way tf32 split [k=tap*256+c][oc] ----------------
__global__ void k_wsplit(const float* __restrict__ w) {
    int oc = blockIdx.x, c = threadIdx.x;
#pragma unroll
    for (int tap = 0; tap < 9; tap++) {
        float v = w[(size_t)oc * KDIM + c * 9 + tap];
        float h0 = tf32_rn(v);
        float r = v - h0;
        float h1 = tf32_rn(r);
        float h2 = tf32_rn(r - h1);
        int k = tap * 256 + c;
        g_w0[(size_t)k * 256 + oc] = h0;
        g_w1[(size_t)k * 256 + oc] = h1;
        g_w2[(size_t)k * 256 + oc] = h2;
    }
}

// ---------------- K1: conv3x3 SAME + bias + relu, 6-term 3xTF32 mma.sync ----------------
// CTA 128pix x 64oc, grid (256,4), 8 warps (4M x 2N), warp tile 32x32 -> acc 32 regs.
// Numerics identical to the R8 version (same chunk order, 6-mma chain, FADD sequence).
__global__ void __launch_bounds__(256, 2) k_conv_mma(const float* __restrict__ bias) {
    extern __shared__ float sm[];
    const uint32_t smb = smem_u32(sm);
    const int tid = threadIdx.x;
    const int lane = tid & 31, wid = tid >> 5;
    const int wm = wid & 3, wn = wid >> 2;
    const int m0 = blockIdx.x * 128;
    const int n0 = blockIdx.y * 64;
    const int nimg = m0 >> 12;
    const int y0 = (m0 & 4095) >> 6;
    const size_t xrowbase = ((size_t)nimg << 12);

    const int pixA = tid & 127;
    const bool loA = (tid < 128);
    const float* xplM = loA ? g_x0 : g_x1;

    float acc[2][4][4];
#pragma unroll
    for (int t = 0; t < 2; t++)
#pragma unroll
        for (int nt = 0; nt < 4; nt++)
#pragma unroll
            for (int q = 0; q < 4; q++) acc[t][nt][q] = 0.f;

    float rA[8], rC[8];

#define LOADA(s_)                                                                \
    {                                                                            \
        const int sA = (s_);                                                     \
        const int tapA = sA >> 5;                                                \
        const int ccA = (sA & 31) << 3;                                          \
        const int kyA = tapA / 3, kxA = tapA - kyA * 3;                          \
        const int pyA = y0 + (pixA >> 6) + kyA - 1;                              \
        const int pxA = (pixA & 63) + kxA - 1;                                   \
        const bool okA = ((unsigned)pyA < 64u) && ((unsigned)pxA < 64u);         \
        const size_t offA = ((xrowbase + (pyA << 6) + pxA) << 8) + ccA;          \
        if (okA) {                                                               \
            const float4* sp1 = (const float4*)(xplM + offA);                    \
            float4 uA = sp1[0], vA = sp1[1];                                     \
            rA[0] = uA.x; rA[1] = uA.y; rA[2] = uA.z; rA[3] = uA.w;              \
            rA[4] = vA.x; rA[5] = vA.y; rA[6] = vA.z; rA[7] = vA.w;              \
            if (loA) {                                                           \
                const float4* sp2 = (const float4*)(g_x2 + offA);                \
                float4 uC = sp2[0], vC = sp2[1];                                 \
                rC[0] = uC.x; rC[1] = uC.y; rC[2] = uC.z; rC[3] = uC.w;          \
                rC[4] = vC.x; rC[5] = vC.y; rC[6] = vC.z; rC[7] = vC.w;          \
            }                                                                    \
        } else {                                                                 \
            _Pragma("unroll") for (int kq = 0; kq < 8; kq++) { rA[kq] = 0.f; rC[kq] = 0.f; } \
        }                                                                        \
    }

#define STOREA(st_)                                                              \
    {                                                                            \
        float* dA = sm + (st_) * STG_F + (loA ? 0 : APL) + pixA;                 \
        _Pragma("unroll") for (int kq = 0; kq < 8; kq++) dA[kq * AROW] = rA[kq]; \
        if (loA) {                                                               \
            float* dC = sm + (st_) * STG_F + 2 * APL + pixA;                     \
            _Pragma("unroll") for (int kq = 0; kq < 8; kq++) dC[kq * AROW] = rC[kq]; \
        }                                                                        \
    }

// B tile per chunk: 3 planes x 8 rows x 64 cols = 384 float4 loads over 256 threads.
#define LOADB(s_, st_)                                                           \
    {                                                                            \
        const int sB = (s_);                                                     \
        _Pragma("unroll")                                                        \
        for (int iB = 0; iB < 2; iB++) {                                         \
            int jB = tid + iB * 256;                                             \
            if (jB < 384) {                                                      \
                int plB = jB >> 7, rowB = (jB >> 4) & 7, offB = jB & 15;         \
                uint32_t dstB = smb + ((st_) * STG_F + BOFF3 + plB * BPL +       \
                                       rowB * BROW + offB * 4) * 4;              \
                const float* wsel = (plB == 0) ? g_w0 : ((plB == 1) ? g_w1 : g_w2); \
                const float* srcB = wsel + ((size_t)(sB * 8 + rowB)) * 256 + n0 + offB * 4; \
                cp16(dstB, srcB);                                                \
            }                                                                    \
        }                                                                        \
        cp_commit();                                                             \
    }

#define COMPUTE(st_)                                                             \
    {                                                                            \
        const float* As = sm + (st_) * STG_F;                                    \
        const float* Bs = As + BOFF3;                                            \
        const int mr = lane >> 2, kk = lane & 3;                                 \
        float a0[2][4], a1[2][4], a2[2][4];                                      \
        _Pragma("unroll")                                                        \
        for (int t = 0; t < 2; t++) {                                            \
            int mb = wm * 32 + t * 16 + mr;                                      \
            a0[t][0] = As[kk * AROW + mb];                                       \
            a0[t][1] = As[kk * AROW + mb + 8];                                   \
            a0[t][2] = As[(kk + 4) * AROW + mb];                                 \
            a0[t][3] = As[(kk + 4) * AROW + mb + 8];                             \
            a1[t][0] = As[APL + kk * AROW + mb];                                 \
            a1[t][1] = As[APL + kk * AROW + mb + 8];                             \
            a1[t][2] = As[APL + (kk + 4) * AROW + mb];                           \
            a1[t][3] = As[APL + (kk + 4) * AROW + mb + 8];                       \
            a2[t][0] = As[2 * APL + kk * AROW + mb];                             \
            a2[t][1] = As[2 * APL + kk * AROW + mb + 8];                         \
            a2[t][2] = As[2 * APL + (kk + 4) * AROW + mb];                       \
            a2[t][3] = As[2 * APL + (kk + 4) * AROW + mb + 8];                   \
        }                                                                        \
        _Pragma("unroll")                                                        \
        for (int nt = 0; nt < 4; nt++) {                                         \
            int nb = wn * 32 + nt * 8 + mr;                                      \
            float b00 = Bs[kk * BROW + nb];                                      \
            float b01 = Bs[(kk + 4) * BROW + nb];                                \
            float b10 = Bs[BPL + kk * BROW + nb];                                \
            float b11 = Bs[BPL + (kk + 4) * BROW + nb];                          \
            float b20 = Bs[2 * BPL + kk * BROW + nb];                            \
            float b21 = Bs[2 * BPL + (kk + 4) * BROW + nb];                      \
            _Pragma("unroll")                                                    \
            for (int t = 0; t < 2; t++) {                                        \
                float tmp[4] = {0.f, 0.f, 0.f, 0.f};                             \
                mma8(tmp, a0[t], b00, b01);                                      \
                mma8(tmp, a0[t], b10, b11);                                      \
                mma8(tmp, a1[t], b00, b01);                                      \
                mma8(tmp, a1[t], b10, b11);                                      \
                mma8(tmp, a0[t], b20, b21);                                      \
                mma8(tmp, a2[t], b00, b01);                                      \
                acc[t][nt][0] += tmp[0];                                         \
                acc[t][nt][1] += tmp[1];                                         \
                acc[t][nt][2] += tmp[2];                                         \
                acc[t][nt][3] += tmp[3];                                         \
            }                                                                    \
        }                                                                        \
    }

    LOADA(0);
    LOADB(0, 0);
    STOREA(0);
    cp_wait0();
    __syncthreads();

    for (int s = 0; s < NKC; s++) {
        const int st = s & 1;
        if (s + 1 < NKC) {
            LOADA(s + 1);
            LOADB(s + 1, st ^ 1);
        }
        COMPUTE(st);
        if (s + 1 < NKC) {
            STOREA(st ^ 1);
            cp_wait0();
        }
        __syncthreads();
    }
#undef LOADA
#undef STOREA
#undef LOADB
#undef COMPUTE

    // epilogue: bias + relu -> g_h NCHW
#pragma unroll
    for (int t = 0; t < 2; t++) {
        int mb = m0 + wm * 32 + t * 16 + (lane >> 2);
        int pp0 = mb & 4095, pp1 = (mb + 8) & 4095;
#pragma unroll
        for (int nt = 0; nt < 4; nt++) {
            int oc = n0 + wn * 32 + nt * 8 + (lane & 3) * 2;
            float b0 = __ldg(bias + oc), b1 = __ldg(bias + oc + 1);
            size_t base0 = ((size_t)nimg * 256 + oc) << 12;
            g_h[base0 + pp0] = fmaxf(acc[t][nt][0] + b0, 0.f);
            g_h[base0 + 4096 + pp0] = fmaxf(acc[t][nt][1] + b1, 0.f);
            g_h[base0 + pp1] = fmaxf(acc[t][nt][2] + b0, 0.f);
            g_h[base0 + 4096 + pp1] = fmaxf(acc[t][nt][3] + b1, 0.f);
        }
    }
}

// ---------------- K2: fused 1x1 heads + softmax-fg + decode/clip/valid + keys ----------------
__global__ void __launch_bounds__(256) k_heads(const float* __restrict__ lw,
                                               const float* __restrict__ lb,
                                               const float* __restrict__ sw,
                                               const float* __restrict__ sb,
                                               float* __restrict__ out,
                                               const void* pih, const void* piw) {
    __shared__ float sh[4][256];
    __shared__ float so[4][56];
    int p0 = blockIdx.x * 4;
    int n = p0 >> 12;
    int pbase = p0 & 4095;
    for (int idx = threadIdx.x; idx < 1024; idx += 256) {
        int px = idx & 3;
        int c = idx >> 2;
        sh[px][c] = g_h[(((size_t)n * CIN + c) << 12) + pbase + px];
    }
    __syncthreads();
    {
        int px = threadIdx.x >> 6;
        int ch = threadIdx.x & 63;
        if (ch < 54) {
            const float* wv;
            float bv;
            if (ch < 36) { wv = lw + (size_t)ch * 256; bv = lb[ch]; }
            else         { wv = sw + (size_t)(ch - 36) * 256; bv = sb[ch - 36]; }
            float acc = 0.f;
#pragma unroll 8
            for (int k = 0; k < 256; k++) acc += sh[px][k] * wv[k];
            acc += bv;
            so[px][ch] = acc;
            int pp = (p0 + px) & 4095;
            if (ch < 36)
                out[OFF_LOC + (size_t)n * 147456 + (size_t)pp * 36 + ch] = acc;
            else
                out[OFF_SCORE + (size_t)n * 73728 + (size_t)pp * 18 + (ch - 36)] = acc;
        }
    }
    __syncthreads();
    if (threadIdx.x < 36) {
        int px = threadIdx.x / 9;
        int a = threadIdx.x % 9;
        int pp = (p0 + px) & 4095;
        int y = pp >> 6, xq = pp & 63;
        const double RAT[3] = {0.5, 1.0, 2.0};
        const double SCL[3] = {8.0, 16.0, 32.0};
        int ri = a / 3, sj = a % 3;
        double hh = 7.0 * SCL[sj] * sqrt(RAT[ri]);
        double wd = 7.0 * SCL[sj] * sqrt(1.0 / RAT[ri]);
        float ab0 = (float)(3.5 - hh / 2.0), ab1 = (float)(3.5 - wd / 2.0);
        float ab2 = (float)(3.5 + hh / 2.0), ab3 = (float)(3.5 + wd / 2.0);
        float shy = (float)(y * 16), shx = (float)(xq * 16);
        float A0 = shy + ab0, A1 = shx + ab1, A2 = shy + ab2, A3 = shx + ab3;
        long aidx = (long)pp * NA + a;
        if (n == 0) {
            float* ao = out + OFF_ANCH + (size_t)aidx * 4;
            ao[0] = A0; ao[1] = A1; ao[2] = A2; ao[3] = A3;
        }
        float ah = A2 - A0, aw = A3 - A1;
        float acy = A0 + 0.5f * ah, acx = A1 + 0.5f * aw;
        float dy = so[px][a * 4 + 0], dx = so[px][a * 4 + 1];
        float dh = so[px][a * 4 + 2], dw = so[px][a * 4 + 3];
        float cy = dy * ah + acy;
        float cx = dx * aw + acx;
        float bh = expf(dh) * ah;
        float bw = expf(dw) * aw;
        float imh = read_dim(pih), imw = read_dim(piw);
        float y1 = fminf(fmaxf(cy - 0.5f * bh, 0.f), imh);
        float x1 = fminf(fmaxf(cx - 0.5f * bw, 0.f), imw);
        float y2 = fminf(fmaxf(cy + 0.5f * bh, 0.f), imh);
        float x2 = fminf(fmaxf(cx + 0.5f * bw, 0.f), imw);
        bool valid = ((y2 - y1) >= 16.f) && ((x2 - x1) >= 16.f);
        float s0 = so[px][36 + 2 * a], s1 = so[px][37 + 2 * a];
        float mm = fmaxf(s0, s1);
        float e0 = expf(s0 - mm), e1 = expf(s1 - mm);
        float fg = __fdiv_rn(e1, __fadd_rn(e0, e1));
        float sc = valid ? fg : -INFINITY;
        unsigned u = __float_as_uint(sc);
        unsigned sbits = (u & 0x80000000u) ? ~u : (u | 0x80000000u);
        size_t gi = (size_t)n * APIMG + aidx;
        g_key[gi] = ~sbits;
        float* bp = g_boxes + gi * 4;
        bp[0] = y1; bp[1] = x1; bp[2] = y2; bp[3] = x2;
    }
}

// ---------------- K3: exact top-6000 (radix select + bitonic sort) ----------------
__global__ void __launch_bounds__(1024) k_topk() {
    extern __shared__ unsigned smem[];
    unsigned* keys = smem;
    unsigned long long* buf = (unsigned long long*)(smem + APIMG);
    __shared__ int hist[256];
    __shared__ unsigned s_val;
    __shared__ int s_rem;
    __shared__ int s_cnt;
    int n = blockIdx.x;
    int tid = threadIdx.x;
    const unsigned* gk = g_key + (size_t)n * APIMG;
    for (int i = tid; i < APIMG; i += 1024) keys[i] = gk[i];
    __syncthreads();

    unsigned prefix = 0, mask = 0;
    int rem = NPRE;
    for (int pass = 0; pass < 4; pass++) {
        int shift = 24 - pass * 8;
        if (tid < 256) hist[tid] = 0;
        __syncthreads();
        for (int i = tid; i < APIMG; i += 1024) {
            unsigned k = keys[i];
            if ((k & mask) == prefix) atomicAdd(&hist[(k >> shift) & 255], 1);
        }
        __syncthreads();
        if (tid == 0) {
            int accu = 0;
            for (int d = 0; d < 256; d++) {
                int c = hist[d];
                if (accu + c >= rem) { s_val = prefix | ((unsigned)d << shift); s_rem = rem - accu; break; }
                accu += c;
            }
        }
        __syncthreads();
        prefix = s_val;
        rem = s_rem;
        mask |= (0xFFu << shift);
    }
    unsigned T = prefix;
    int r = rem;

    unsigned ipref = 0, im = 0;
    int ir = r;
    for (int pass = 0; pass < 2; pass++) {
        int shift = 8 - pass * 8;
        if (tid < 256) hist[tid] = 0;
        __syncthreads();
        for (int i = tid; i < APIMG; i += 1024) {
            if (keys[i] == T && (((unsigned)i & im) == ipref))
                atomicAdd(&hist[((unsigned)i >> shift) & 255], 1);
        }
        __syncthreads();
        if (tid == 0) {
            int accu = 0;
            for (int d = 0; d < 256; d++) {
                int c = hist[d];
                if (accu + c >= ir) { s_val = ipref | ((unsigned)d << shift); s_rem = ir - accu; break; }
                accu += c;
            }
        }
        __syncthreads();
        ipref = s_val;
        ir = s_rem;
        im |= (0xFFu << shift);
    }
    unsigned idxT = ipref;

    if (tid == 0) s_cnt = 0;
    __syncthreads();
    for (int i = tid; i < APIMG; i += 1024) {
        unsigned k = keys[i];
        if (k < T || (k == T && (unsigned)i <= idxT)) {
            int pos = atomicAdd(&s_cnt, 1);
            buf[pos] = (((unsigned long long)k) << 32) | (unsigned)i;
        }
    }
    __syncthreads();
    int cnt = s_cnt;
    for (int i = tid; i < 8192; i += 1024)
        if (i >= cnt) buf[i] = 0xFFFFFFFFFFFFFFFFull;
    __syncthreads();
    for (int size = 2; size <= 8192; size <<= 1) {
        for (int stride = size >> 1; stride > 0; stride >>= 1) {
            for (int i = tid; i < 8192; i += 1024) {
                int ixj = i ^ stride;
                if (ixj > i) {
                    bool up = ((i & size) == 0);
                    unsigned long long vaa = buf[i], vbb = buf[ixj];
                    if ((vaa > vbb) == up) { buf[i] = vbb; buf[ixj] = vaa; }
                }
            }
            __syncthreads();
        }
    }
    for (int r2 = tid; r2 < NPRE; r2 += 1024) {
        unsigned idx = (unsigned)(buf[r2] & 0xFFFFFFFFull);
        float4 bb = *(const float4*)(g_boxes + ((size_t)n * APIMG + idx) * 4);
        *(float4*)(g_top + ((size_t)n * NPRE + r2) * 4) = bb;
    }
}

// ---------------- K4: NMS bitmask (upper triangle) ----------------
__global__ void __launch_bounds__(64) k_mask() {
    int n = blockIdx.z;
    int it = blockIdx.x, jt = blockIdx.y;
    if (jt < it) return;
    __shared__ float4 sb[64];
    __shared__ float sarea[64];
    int tid = threadIdx.x;
    int j = jt * 64 + tid;
    float4 bj = (j < NPRE) ? *(const float4*)(g_top + ((size_t)n * NPRE + j) * 4)
                           : make_float4(0, 0, 0, 0);
    sb[tid] = bj;
    sarea[tid] = (bj.z - bj.x) * (bj.w - bj.y);
    __syncthreads();
    int i = it * 64 + tid;
    if (i >= NPRE) return;
    float4 bi = *(const float4*)(g_top + ((size_t)n * NPRE + i) * 4);
    float ai = (bi.z - bi.x) * (bi.w - bi.y);
    unsigned long long bits = 0;
    int jmax = min(64, NPRE - jt * 64);
#pragma unroll 4
    for (int q = 0; q < 64; q++) {
        if (q < jmax) {
            float4 b2 = sb[q];
            float ty0 = fmaxf(bi.x, b2.x), tx0 = fmaxf(bi.y, b2.y);
            float by0 = fminf(bi.z, b2.z), bx0 = fminf(bi.w, b2.w);
            float ih = fmaxf(by0 - ty0, 0.f), iw = fmaxf(bx0 - tx0, 0.f);
            float inter = ih * iw;
            float iou = inter / (ai + sarea[q] - inter + 1e-9f);
            if (iou > 0.7f) bits |= (1ull << q);
        }
    }
    g_mask[((size_t)n * NPRE + i) * NWORDS + jt] = bits;
}

// ---------------- K5: sequential suppression + ROI writeout ----------------
__global__ void __launch_bounds__(32) k_nms(float* __restrict__ out) {
    int n = blockIdx.x;
    int lane = threadIdx.x;
    __shared__ int s_keep[NPOST];
    __shared__ int s_cnt;
    unsigned long long remv0 = 0, remv1 = 0, remv2 = 0;
    int cnt = 0;
    const unsigned long long* mbase = g_mask + (size_t)n * NPRE * NWORDS;
    for (int w = 0; w < NWORDS && cnt < NPOST; w++) {
        int owner = w & 31, slot = w >> 5;
        unsigned long long myv = (slot == 0) ? remv0 : ((slot == 1) ? remv1 : remv2);
        unsigned long long cur = __shfl_sync(0xffffffffu, myv, owner);
        int bmax = min(64, NPRE - (w << 6));
        for (int b = 0; b < bmax; b++) {
            if (!((cur >> b) & 1ull)) {
                int i = (w << 6) + b;
                if (lane == 0) s_keep[cnt] = i;
                cnt++;
                const unsigned long long* row = mbase + (size_t)i * NWORDS;
                if (lane >= w && lane < NWORDS) remv0 |= __ldg(row + lane);
                if (lane + 32 >= w && lane + 32 < NWORDS) remv1 |= __ldg(row + lane + 32);
                if (lane + 64 >= w && lane + 64 < NWORDS) remv2 |= __ldg(row + lane + 64);
                if (cnt >= NPOST) break;
                myv = (slot == 0) ? remv0 : ((slot == 1) ? remv1 : remv2);
                cur |= __shfl_sync(0xffffffffu, myv, owner);
            }
        }
    }
    if (lane == 0) s_cnt = cnt;
    __syncwarp();
    if (lane == 0 && cnt < NPOST) {
        int ptr = 0, fill = cnt;
        for (int i = 0; i < NPRE && fill < NPOST; i++) {
            if (ptr < cnt && s_keep[ptr] == i) ptr++;
            else s_keep[fill++] = i;
        }
    }
    __syncwarp();
    for (int r2 = lane; r2 < NPOST; r2 += 32) {
        int idx = s_keep[r2];
        float4 bb = *(const float4*)(g_top + ((size_t)n * NPRE + idx) * 4);
        float* o = out + OFF_ROIS + ((size_t)n * NPOST + r2) * 4;
        o[0] = bb.x; o[1] = bb.y; o[2] = bb.z; o[3] = bb.w;
        out[OFF_RIDX + n * NPOST + r2] = (float)n;
    }
}

// ---------------- launch ----------------
extern "C" void kernel_launch(void* const* d_in, const int* in_sizes, int n_in,
                              void* d_out, int out_size) {
    const float* x  = (const float*)d_in[0];
    const float* w1 = (const float*)d_in[1];
    const float* b1 = (const float*)d_in[2];
    const float* sw = (const float*)d_in[3];
    const float* sb = (const float*)d_in[4];
    const float* lw = (const float*)d_in[5];
    const float* lb = (const float*)d_in[6];
    const void* pih = d_in[7];
    const void* piw = d_in[8];
    float* out = (float*)d_out;

    k_xsplit<<<dim3(128, 8, 8), dim3(32, 8)>>>(x);
    k_wsplit<<<256, 256>>>(w1);
    k_conv_mma<<<dim3(256, 4), 256, DSMEM_BYTES>>>(b1);
    k_heads<<<8192, 256>>>(lw, lb, sw, sb, out, pih, piw);
    cudaFuncSetAttribute(k_topk, cudaFuncAttributeMaxDynamicSharedMemorySize, 213504);
    k_topk<<<8, 1024, 212992>>>();
    k_mask<<<dim3(94, 94, 8), 64>>>();
    k_nms<<<8, 32>>>(out);
}

// round 10
// speedup vs baseline: 1.2987x; 1.2987x over previous
#include <cuda_runtime.h>
#include <math.h>
#include <stdint.h>

#define NIMG 8
#define CIN 256
#define HW 4096
#define NA 9
#define APIMG 36864
#define NPRE 6000
#define NPOST 300
#define KDIM 2304
#define NWORDS 94
#define NKC 288           // K steps of 8

#define OFF_LOC   0
#define OFF_SCORE 1179648
#define OFF_ROIS  1769472
#define OFF_RIDX  1779072
#define OFF_ANCH  1781472

// ---------------- static device scratch ----------------
__device__ float g_wT[KDIM * 256];           // k-major weights [k=tap*256+c][oc]
__device__ float g_h[NIMG * CIN * HW];       // conv out NCHW
__device__ float g_boxes[NIMG * APIMG * 4];
__device__ unsigned g_key[NIMG * APIMG];
__device__ float g_top[NIMG * NPRE * 4];
__device__ unsigned long long g_mask[(size_t)NIMG * NPRE * NWORDS];

// ---------------- helpers ----------------
__device__ __forceinline__ uint32_t smem_u32(const void* p) {
    uint32_t a;
    asm("{ .reg .u64 t; cvta.to.shared.u64 t, %1; cvt.u32.u64 %0, t; }" : "=r"(a) : "l"(p));
    return a;
}
__device__ __forceinline__ void cp4z(uint32_t dst, const void* src, bool v) {
    int sz = v ? 4 : 0;
    asm volatile("cp.async.ca.shared.global [%0], [%1], 4, %2;"
                 :: "r"(dst), "l"(src), "r"(sz) : "memory");
}
__device__ __forceinline__ void cp16(uint32_t dst, const void* src) {
    asm volatile("cp.async.cg.shared.global [%0], [%1], 16;" :: "r"(dst), "l"(src) : "memory");
}
__device__ __forceinline__ void cp_commit() { asm volatile("cp.async.commit_group;" ::: "memory"); }
__device__ __forceinline__ void cp_wait1() { asm volatile("cp.async.wait_group 1;" ::: "memory"); }
__device__ __forceinline__ void cp_wait0() { asm volatile("cp.async.wait_group 0;" ::: "memory"); }
__device__ __forceinline__ float read_dim(const void* p) {
    int v = *(const int*)p;
    if (v > 0 && v < 1048576) return (float)v;
    long long l = *(const long long*)p;
    if (l > 0 && l < 1048576) return (float)l;
    return *(const float*)p;
}

// ---------------- K0: transpose conv1 weights to k-major (k = tap*256 + c) ----------------
__global__ void k_wt(const float* __restrict__ w) {
    int o = blockIdx.x;
    for (int k = threadIdx.x; k < KDIM; k += 256) {
        int c = k & 255;
        int tap = k >> 8;
        g_wT[(size_t)k * 256 + o] = w[(size_t)o * KDIM + c * 9 + tap];
    }
}

// ---------------- K1: conv3x3 SAME + bias + relu, implicit-im2col FFMA SGEMM ----------------
// 128x128 tile, 256 threads, 8x8 microtile, BK=8, 3-stage cp.async pipeline.
// Accumulation order identical to the R2 FFMA version (ascending k, av[i]*bv[j]).
__global__ void __launch_bounds__(256, 2) k_conv(const float* __restrict__ x,
                                                 const float* __restrict__ bias) {
    __shared__ __align__(16) float As[3][8][128];
    __shared__ __align__(16) float Bs[3][8][128];
    const int tid = threadIdx.x;
    const int tx = tid & 15, ty = tid >> 4;
    const int m0 = blockIdx.x * 128;
    const int n0 = blockIdx.y * 128;
    const int nimg = m0 >> 12;
    const int y0 = (m0 & 4095) >> 6;

    // A-load geometry (per thread, loop-invariant parts)
    const int ll = tid & 127;
    const int kb = tid >> 7;                  // 0 or 1
    const int ay = y0 + (ll >> 6);            // pixel row
    const int ax = ll & 63;                   // pixel col
    const float* xb = x + (((size_t)nimg * CIN) << 12);
    // B-load geometry
    const int brow = tid >> 5;                // 0..7
    const int boff = (tid & 31) << 2;         // 0..124 step 4
    const float* wb = g_wT + n0 + boff;

    float acc[8][8];
#pragma unroll
    for (int i = 0; i < 8; i++)
#pragma unroll
        for (int j = 0; j < 8; j++) acc[i][j] = 0.f;

#define LOADST(s_, st_)                                                          \
    {                                                                            \
        const int sL = (s_);                                                     \
        const int stL = (st_);                                                   \
        const int tapL = sL >> 5;                                                \
        const int kyL = tapL / 3, kxL = tapL - kyL * 3;                          \
        const int pyL = ay + kyL - 1, pxL = ax + kxL - 1;                        \
        const bool okL = ((unsigned)pyL < 64u) && ((unsigned)pxL < 64u);         \
        const int cL = ((sL & 31) << 3) + kb;                                    \
        const float* asrc = okL ? (xb + (((size_t)cL) << 12) + (pyL << 6) + pxL) \
                                : xb;                                            \
        _Pragma("unroll")                                                        \
        for (int tL = 0; tL < 4; tL++)                                           \
            cp4z(smem_u32(&As[stL][kb + 2 * tL][ll]), asrc + (tL << 13), okL);   \
        cp16(smem_u32(&Bs[stL][brow][boff]),                                     \
             wb + ((size_t)(sL * 8 + brow)) * 256);                              \
        cp_commit();                                                             \
    }

#define COMPUTE(st_)                                                             \
    {                                                                            \
        const int stC = (st_);                                                   \
        _Pragma("unroll")                                                        \
        for (int kk = 0; kk < 8; kk++) {                                         \
            float4 a0 = ((const float4*)As[stC][kk])[ty * 2];                    \
            float4 a1 = ((const float4*)As[stC][kk])[ty * 2 + 1];                \
            float4 b0 = ((const float4*)Bs[stC][kk])[tx * 2];                    \
            float4 b1 = ((const float4*)Bs[stC][kk])[tx * 2 + 1];                \
            float av[8] = {a0.x, a0.y, a0.z, a0.w, a1.x, a1.y, a1.z, a1.w};      \
            float bv[8] = {b0.x, b0.y, b0.z, b0.w, b1.x, b1.y, b1.z, b1.w};      \
            _Pragma("unroll")                                                    \
            for (int i2 = 0; i2 < 8; i2++)                                       \
                _Pragma("unroll")                                                \
                for (int j2 = 0; j2 < 8; j2++)                                   \
                    acc[i2][j2] += av[i2] * bv[j2];                              \
        }                                                                        \
    }

    LOADST(0, 0);
    LOADST(1, 1);

    for (int s = 0; s < NKC; s++) {
        if (s + 2 < NKC) cp_wait1(); else cp_wait0();
        __syncthreads();
        if (s + 2 < NKC) {
            int st2 = (s + 2) % 3;
            LOADST(s + 2, st2);
        }
        COMPUTE(s % 3);
    }
#undef LOADST
#undef COMPUTE

    // epilogue: bias + relu -> g_h NCHW
#pragma unroll
    for (int i = 0; i < 8; i++) {
        int mo = m0 + ty * 8 + i;
        int n = mo >> 12;
        int pp = mo & 4095;
#pragma unroll
        for (int j = 0; j < 8; j++) {
            int o = n0 + tx * 8 + j;
            g_h[(((size_t)n * CIN + o) << 12) + pp] = fmaxf(acc[i][j] + bias[o], 0.f);
        }
    }
}

// ---------------- K2: fused 1x1 heads + softmax-fg + decode/clip/valid + keys ----------------
__global__ void __launch_bounds__(256) k_heads(const float* __restrict__ lw,
                                               const float* __restrict__ lb,
                                               const float* __restrict__ sw,
                                               const float* __restrict__ sb,
                                               float* __restrict__ out,
                                               const void* pih, const void* piw) {
    __shared__ float sh[4][256];
    __shared__ float so[4][56];
    int p0 = blockIdx.x * 4;
    int n = p0 >> 12;
    int pbase = p0 & 4095;
    for (int idx = threadIdx.x; idx < 1024; idx += 256) {
        int px = idx & 3;
        int c = idx >> 2;
        sh[px][c] = g_h[(((size_t)n * CIN + c) << 12) + pbase + px];
    }
    __syncthreads();
    {
        int px = threadIdx.x >> 6;
        int ch = threadIdx.x & 63;
        if (ch < 54) {
            const float* wv;
            float bv;
            if (ch < 36) { wv = lw + (size_t)ch * 256; bv = lb[ch]; }
            else         { wv = sw + (size_t)(ch - 36) * 256; bv = sb[ch - 36]; }
            float acc = 0.f;
#pragma unroll 8
            for (int k = 0; k < 256; k++) acc += sh[px][k] * wv[k];
            acc += bv;
            so[px][ch] = acc;
            int pp = (p0 + px) & 4095;
            if (ch < 36)
                out[OFF_LOC + (size_t)n * 147456 + (size_t)pp * 36 + ch] = acc;
            else
                out[OFF_SCORE + (size_t)n * 73728 + (size_t)pp * 18 + (ch - 36)] = acc;
        }
    }
    __syncthreads();
    if (threadIdx.x < 36) {
        int px = threadIdx.x / 9;
        int a = threadIdx.x % 9;
        int pp = (p0 + px) & 4095;
        int y = pp >> 6, xq = pp & 63;
        const double RAT[3] = {0.5, 1.0, 2.0};
        const double SCL[3] = {8.0, 16.0, 32.0};
        int ri = a / 3, sj = a % 3;
        double hh = 7.0 * SCL[sj] * sqrt(RAT[ri]);
        double wd = 7.0 * SCL[sj] * sqrt(1.0 / RAT[ri]);
        float ab0 = (float)(3.5 - hh / 2.0), ab1 = (float)(3.5 - wd / 2.0);
        float ab2 = (float)(3.5 + hh / 2.0), ab3 = (float)(3.5 + wd / 2.0);
        float shy = (float)(y * 16), shx = (float)(xq * 16);
        float A0 = shy + ab0, A1 = shx + ab1, A2 = shy + ab2, A3 = shx + ab3;
        long aidx = (long)pp * NA + a;
        if (n == 0) {
            float* ao = out + OFF_ANCH + (size_t)aidx * 4;
            ao[0] = A0; ao[1] = A1; ao[2] = A2; ao[3] = A3;
        }
        float ah = A2 - A0, aw = A3 - A1;
        float acy = A0 + 0.5f * ah, acx = A1 + 0.5f * aw;
        float dy = so[px][a * 4 + 0], dx = so[px][a * 4 + 1];
        float dh = so[px][a * 4 + 2], dw = so[px][a * 4 + 3];
        float cy = dy * ah + acy;
        float cx = dx * aw + acx;
        float bh = expf(dh) * ah;
        float bw = expf(dw) * aw;
        float imh = read_dim(pih), imw = read_dim(piw);
        float y1 = fminf(fmaxf(cy - 0.5f * bh, 0.f), imh);
        float x1 = fminf(fmaxf(cx - 0.5f * bw, 0.f), imw);
        float y2 = fminf(fmaxf(cy + 0.5f * bh, 0.f), imh);
        float x2 = fminf(fmaxf(cx + 0.5f * bw, 0.f), imw);
        bool valid = ((y2 - y1) >= 16.f) && ((x2 - x1) >= 16.f);
        float s0 = so[px][36 + 2 * a], s1 = so[px][37 + 2 * a];
        float mm = fmaxf(s0, s1);
        float e0 = expf(s0 - mm), e1 = expf(s1 - mm);
        float fg = __fdiv_rn(e1, __fadd_rn(e0, e1));
        float sc = valid ? fg : -INFINITY;
        unsigned u = __float_as_uint(sc);
        unsigned sbits = (u & 0x80000000u) ? ~u : (u | 0x80000000u);
        size_t gi = (size_t)n * APIMG + aidx;
        g_key[gi] = ~sbits;
        float* bp = g_boxes + gi * 4;
        bp[0] = y1; bp[1] = x1; bp[2] = y2; bp[3] = x2;
    }
}

// ---------------- K3: exact top-6000 (radix select + bitonic sort) ----------------
__global__ void __launch_bounds__(1024) k_topk() {
    extern __shared__ unsigned smem[];
    unsigned* keys = smem;
    unsigned long long* buf = (unsigned long long*)(smem + APIMG);
    __shared__ int hist[256];
    __shared__ unsigned s_val;
    __shared__ int s_rem;
    __shared__ int s_cnt;
    int n = blockIdx.x;
    int tid = threadIdx.x;
    const unsigned* gk = g_key + (size_t)n * APIMG;
    for (int i = tid; i < APIMG; i += 1024) keys[i] = gk[i];
    __syncthreads();

    unsigned prefix = 0, mask = 0;
    int rem = NPRE;
    for (int pass = 0; pass < 4; pass++) {
        int shift = 24 - pass * 8;
        if (tid < 256) hist[tid] = 0;
        __syncthreads();
        for (int i = tid; i < APIMG; i += 1024) {
            unsigned k = keys[i];
            if ((k & mask) == prefix) atomicAdd(&hist[(k >> shift) & 255], 1);
        }
        __syncthreads();
        if (tid == 0) {
            int accu = 0;
            for (int d = 0; d < 256; d++) {
                int c = hist[d];
                if (accu + c >= rem) { s_val = prefix | ((unsigned)d << shift); s_rem = rem - accu; break; }
                accu += c;
            }
        }
        __syncthreads();
        prefix = s_val;
        rem = s_rem;
        mask |= (0xFFu << shift);
    }
    unsigned T = prefix;
    int r = rem;

    unsigned ipref = 0, im = 0;
    int ir = r;
    for (int pass = 0; pass < 2; pass++) {
        int shift = 8 - pass * 8;
        if (tid < 256) hist[tid] = 0;
        __syncthreads();
        for (int i = tid; i < APIMG; i += 1024) {
            if (keys[i] == T && (((unsigned)i & im) == ipref))
                atomicAdd(&hist[((unsigned)i >> shift) & 255], 1);
        }
        __syncthreads();
        if (tid == 0) {
            int accu = 0;
            for (int d = 0; d < 256; d++) {
                int c = hist[d];
                if (accu + c >= ir) { s_val = ipref | ((unsigned)d << shift); s_rem = ir - accu; break; }
                accu += c;
            }
        }
        __syncthreads();
        ipref = s_val;
        ir = s_rem;
        im |= (0xFFu << shift);
    }
    unsigned idxT = ipref;

    if (tid == 0) s_cnt = 0;
    __syncthreads();
    for (int i = tid; i < APIMG; i += 1024) {
        unsigned k = keys[i];
        if (k < T || (k == T && (unsigned)i <= idxT)) {
            int pos = atomicAdd(&s_cnt, 1);
            buf[pos] = (((unsigned long long)k) << 32) | (unsigned)i;
        }
    }
    __syncthreads();
    int cnt = s_cnt;
    for (int i = tid; i < 8192; i += 1024)
        if (i >= cnt) buf[i] = 0xFFFFFFFFFFFFFFFFull;
    __syncthreads();
    for (int size = 2; size <= 8192; size <<= 1) {
        for (int stride = size >> 1; stride > 0; stride >>= 1) {
            for (int i = tid; i < 8192; i += 1024) {
                int ixj = i ^ stride;
                if (ixj > i) {
                    bool up = ((i & size) == 0);
                    unsigned long long vaa = buf[i], vbb = buf[ixj];
                    if ((vaa > vbb) == up) { buf[i] = vbb; buf[ixj] = vaa; }
                }
            }
            __syncthreads();
        }
    }
    for (int r2 = tid; r2 < NPRE; r2 += 1024) {
        unsigned idx = (unsigned)(buf[r2] & 0xFFFFFFFFull);
        float4 bb = *(const float4*)(g_boxes + ((size_t)n * APIMG + idx) * 4);
        *(float4*)(g_top + ((size_t)n * NPRE + r2) * 4) = bb;
    }
}

// ---------------- K4: NMS bitmask (upper triangle) ----------------
__global__ void __launch_bounds__(64) k_mask() {
    int n = blockIdx.z;
    int it = blockIdx.x, jt = blockIdx.y;
    if (jt < it) return;
    __shared__ float4 sb[64];
    __shared__ float sarea[64];
    int tid = threadIdx.x;
    int j = jt * 64 + tid;
    float4 bj = (j < NPRE) ? *(const float4*)(g_top + ((size_t)n * NPRE + j) * 4)
                           : make_float4(0, 0, 0, 0);
    sb[tid] = bj;
    sarea[tid] = (bj.z - bj.x) * (bj.w - bj.y);
    __syncthreads();
    int i = it * 64 + tid;
    if (i >= NPRE) return;
    float4 bi = *(const float4*)(g_top + ((size_t)n * NPRE + i) * 4);
    float ai = (bi.z - bi.x) * (bi.w - bi.y);
    unsigned long long bits = 0;
    int jmax = min(64, NPRE - jt * 64);
#pragma unroll 4
    for (int q = 0; q < 64; q++) {
        if (q < jmax) {
            float4 b2 = sb[q];
            float ty0 = fmaxf(bi.x, b2.x), tx0 = fmaxf(bi.y, b2.y);
            float by0 = fminf(bi.z, b2.z), bx0 = fminf(bi.w, b2.w);
            float ih = fmaxf(by0 - ty0, 0.f), iw = fmaxf(bx0 - tx0, 0.f);
            float inter = ih * iw;
            float iou = inter / (ai + sarea[q] - inter + 1e-9f);
            if (iou > 0.7f) bits |= (1ull << q);
        }
    }
    g_mask[((size_t)n * NPRE + i) * NWORDS + jt] = bits;
}

// ---------------- K5: sequential suppression + ROI writeout ----------------
__global__ void __launch_bounds__(32) k_nms(float* __restrict__ out) {
    int n = blockIdx.x;
    int lane = threadIdx.x;
    __shared__ int s_keep[NPOST];
    __shared__ int s_cnt;
    unsigned long long remv0 = 0, remv1 = 0, remv2 = 0;
    int cnt = 0;
    const unsigned long long* mbase = g_mask + (size_t)n * NPRE * NWORDS;
    for (int w = 0; w < NWORDS && cnt < NPOST; w++) {
        int owner = w & 31, slot = w >> 5;
        unsigned long long myv = (slot == 0) ? remv0 : ((slot == 1) ? remv1 : remv2);
        unsigned long long cur = __shfl_sync(0xffffffffu, myv, owner);
        int bmax = min(64, NPRE - (w << 6));
        for (int b = 0; b < bmax; b++) {
            if (!((cur >> b) & 1ull)) {
                int i = (w << 6) + b;
                if (lane == 0) s_keep[cnt] = i;
                cnt++;
                const unsigned long long* row = mbase + (size_t)i * NWORDS;
                if (lane >= w && lane < NWORDS) remv0 |= __ldg(row + lane);
                if (lane + 32 >= w && lane + 32 < NWORDS) remv1 |= __ldg(row + lane + 32);
                if (lane + 64 >= w && lane + 64 < NWORDS) remv2 |= __ldg(row + lane + 64);
                if (cnt >= NPOST) break;
                myv = (slot == 0) ? remv0 : ((slot == 1) ? remv1 : remv2);
                cur |= __shfl_sync(0xffffffffu, myv, owner);
            }
        }
    }
    if (lane == 0) s_cnt = cnt;
    __syncwarp();
    if (lane == 0 && cnt < NPOST) {
        int ptr = 0, fill = cnt;
        for (int i = 0; i < NPRE && fill < NPOST; i++) {
            if (ptr < cnt && s_keep[ptr] == i) ptr++;
            else s_keep[fill++] = i;
        }
    }
    __syncwarp();
    for (int r2 = lane; r2 < NPOST; r2 += 32) {
        int idx = s_keep[r2];
        float4 bb = *(const float4*)(g_top + ((size_t)n * NPRE + idx) * 4);
        float* o = out + OFF_ROIS + ((size_t)n * NPOST + r2) * 4;
        o[0] = bb.x; o[1] = bb.y; o[2] = bb.z; o[3] = bb.w;
        out[OFF_RIDX + n * NPOST + r2] = (float)n;
    }
}

// ---------------- launch ----------------
extern "C" void kernel_launch(void* const* d_in, const int* in_sizes, int n_in,
                              void* d_out, int out_size) {
    const float* x  = (const float*)d_in[0];
    const float* w1 = (const float*)d_in[1];
    const float* b1 = (const float*)d_in[2];
    const float* sw = (const float*)d_in[3];
    const float* sb = (const float*)d_in[4];
    const float* lw = (const float*)d_in[5];
    const float* lb = (const float*)d_in[6];
    const void* pih = d_in[7];
    const void* piw = d_in[8];
    float* out = (float*)d_out;

    k_wt<<<256, 256>>>(w1);
    k_conv<<<dim3(256, 2), 256>>>(x, b1);
    k_heads<<<8192, 256>>>(lw, lb, sw, sb, out, pih, piw);
    cudaFuncSetAttribute(k_topk, cudaFuncAttributeMaxDynamicSharedMemorySize, 213504);
    k_topk<<<8, 1024, 212992>>>();
    k_mask<<<dim3(94, 94, 8), 64>>>();
    k_nms<<<8, 32>>>(out);
}

// round 11
// speedup vs baseline: 1.3486x; 1.0385x over previous
#include <cuda_runtime.h>
#include <math.h>
#include <stdint.h>

#define NIMG 8
#define CIN 256
#define HW 4096
#define NA 9
#define APIMG 36864
#define NPRE 6000
#define NPOST 300
#define KDIM 2304
#define NWORDS 94
#define KSTEPS 288

#define OFF_LOC   0
#define OFF_SCORE 1179648
#define OFF_ROIS  1769472
#define OFF_RIDX  1779072
#define OFF_ANCH  1781472

// ---------------- static device scratch ----------------
__device__ float g_wT[KDIM * 256];           // k-major weights [k=tap*256+c][oc]
__device__ float g_h[NIMG * CIN * HW];       // conv out NCHW
__device__ float g_boxes[NIMG * APIMG * 4];
__device__ unsigned g_key[NIMG * APIMG];
__device__ float g_top[NIMG * NPRE * 4];
__device__ unsigned long long g_mask[(size_t)NIMG * NPRE * NWORDS];

// ---------------- helpers ----------------
__device__ __forceinline__ unsigned long long pk2(float lo, float hi) {
    unsigned long long r;
    asm("mov.b64 %0, {%1, %2};" : "=l"(r) : "f"(lo), "f"(hi));
    return r;
}
__device__ __forceinline__ void fma2(unsigned long long& c, unsigned long long a,
                                     unsigned long long b) {
    asm("fma.rn.f32x2 %0, %1, %2, %0;" : "+l"(c) : "l"(a), "l"(b));
}
__device__ __forceinline__ void upk2(float& lo, float& hi, unsigned long long v) {
    asm("mov.b64 {%0, %1}, %2;" : "=f"(lo), "=f"(hi) : "l"(v));
}
__device__ __forceinline__ float read_dim(const void* p) {
    int v = *(const int*)p;
    if (v > 0 && v < 1048576) return (float)v;
    long long l = *(const long long*)p;
    if (l > 0 && l < 1048576) return (float)l;
    return *(const float*)p;
}

// ---------------- dummy kernels (shift k_conv to ncu capture slot -s 5) ----------------
__global__ void k_nop() {}

// ---------------- K0: transpose conv1 weights to k-major (k = tap*256 + c) ----------------
__global__ void k_wt(const float* __restrict__ w) {
    int o = blockIdx.x;
    for (int k = threadIdx.x; k < KDIM; k += 256) {
        int c = k & 255;
        int tap = k >> 8;
        g_wT[(size_t)k * 256 + o] = w[(size_t)o * KDIM + c * 9 + tap];
    }
}

// ---------------- K1: conv3x3 SAME + bias + relu, implicit im2col, f32x2 FFMA2 ----------------
// 128x128 tile, 256 threads, 8x8 microtile (packed as 8x4 f32x2), BK=8,
// double-buffered smem with register prefetch (R2 structure).
// Per-accumulator add order identical to the FFMA version -> bit-identical output.
__global__ void __launch_bounds__(256, 2) k_conv(const float* __restrict__ x,
                                                 const float* __restrict__ bias) {
    __shared__ __align__(16) float As[2][8][128];
    __shared__ __align__(16) float Bs[2][8][128];
    const int m0 = blockIdx.x * 128;
    const int n0 = blockIdx.y * 128;
    const int tid = threadIdx.x;
    const int tx = tid & 15, ty = tid >> 4;

    const int ll = tid & 127;
    const int kb = tid >> 7;
    const int m = m0 + ll;
    const int nimg = m >> 12;
    const int p = m & 4095;
    const int yy = p >> 6, xx = p & 63;
    const float* xb = x + (((size_t)nimg * CIN) << 12);
    const float* wb = g_wT + (size_t)kb * 256 + n0 + ll;

    unsigned long long acc2[8][4];
#pragma unroll
    for (int i = 0; i < 8; i++)
#pragma unroll
        for (int j = 0; j < 4; j++) acc2[i][j] = 0ull;

    float va[4], vb[4];

#define LOADT(k0_)                                                              \
    {                                                                           \
        const int k0L = (k0_);                                                  \
        const int tapL = k0L >> 8;                                              \
        const int kyL = tapL / 3;                                               \
        const int kxL = tapL - kyL * 3;                                         \
        const int y2L = yy + kyL - 1, x2L = xx + kxL - 1;                       \
        const bool inbL = ((unsigned)y2L < 64u) && ((unsigned)x2L < 64u);       \
        const int aoffL = (((k0L & 255) + kb) << 12) + (y2L << 6) + x2L;        \
        const float* bpL = wb + (size_t)k0L * 256;                              \
        _Pragma("unroll")                                                       \
        for (int tL = 0; tL < 4; tL++) {                                        \
            va[tL] = inbL ? __ldg(xb + aoffL + (tL << 13)) : 0.f;               \
            vb[tL] = __ldg(bpL + (size_t)tL * 512);                             \
        }                                                                       \
    }

#define STORET(buf_)                                                            \
    {                                                                           \
        const int bfL = (buf_);                                                 \
        _Pragma("unroll")                                                       \
        for (int tL = 0; tL < 4; tL++) {                                        \
            As[bfL][kb + 2 * tL][ll] = va[tL];                                  \
            Bs[bfL][kb + 2 * tL][ll] = vb[tL];                                  \
        }                                                                       \
    }

    LOADT(0);
    STORET(0);
    __syncthreads();

    for (int s = 0; s < KSTEPS; s++) {
        const int cur = s & 1;
        if (s + 1 < KSTEPS) LOADT((s + 1) * 8);
#pragma unroll
        for (int kk = 0; kk < 8; kk++) {
            float4 a0 = ((const float4*)As[cur][kk])[ty * 2];
            float4 a1 = ((const float4*)As[cur][kk])[ty * 2 + 1];
            float4 b0 = ((const float4*)Bs[cur][kk])[tx * 2];
            float4 b1 = ((const float4*)Bs[cur][kk])[tx * 2 + 1];
            float av[8] = {a0.x, a0.y, a0.z, a0.w, a1.x, a1.y, a1.z, a1.w};
            unsigned long long b2[4] = {pk2(b0.x, b0.y), pk2(b0.z, b0.w),
                                        pk2(b1.x, b1.y), pk2(b1.z, b1.w)};
#pragma unroll
            for (int i2 = 0; i2 < 8; i2++) {
                unsigned long long a2 = pk2(av[i2], av[i2]);
#pragma unroll
                for (int j2 = 0; j2 < 4; j2++) fma2(acc2[i2][j2], a2, b2[j2]);
            }
        }
        if (s + 1 < KSTEPS) STORET((s + 1) & 1);
        __syncthreads();
    }
#undef LOADT
#undef STORET

    // epilogue: unpack + bias + relu -> g_h NCHW (values bit-identical to FFMA path)
#pragma unroll
    for (int i = 0; i < 8; i++) {
        int mo = m0 + ty * 8 + i;
        int n = mo >> 12;
        int pp = mo & 4095;
#pragma unroll
        for (int j2 = 0; j2 < 4; j2++) {
            float lo, hi;
            upk2(lo, hi, acc2[i][j2]);
            int o = n0 + tx * 8 + j2 * 2;
            g_h[(((size_t)n * CIN + o) << 12) + pp] = fmaxf(lo + bias[o], 0.f);
            g_h[(((size_t)n * CIN + o + 1) << 12) + pp] = fmaxf(hi + bias[o + 1], 0.f);
        }
    }
}

// ---------------- K2: fused 1x1 heads + softmax-fg + decode/clip/valid + keys ----------------
__global__ void __launch_bounds__(256) k_heads(const float* __restrict__ lw,
                                               const float* __restrict__ lb,
                                               const float* __restrict__ sw,
                                               const float* __restrict__ sb,
                                               float* __restrict__ out,
                                               const void* pih, const void* piw) {
    __shared__ float sh[4][256];
    __shared__ float so[4][56];
    int p0 = blockIdx.x * 4;
    int n = p0 >> 12;
    int pbase = p0 & 4095;
    for (int idx = threadIdx.x; idx < 1024; idx += 256) {
        int px = idx & 3;
        int c = idx >> 2;
        sh[px][c] = g_h[(((size_t)n * CIN + c) << 12) + pbase + px];
    }
    __syncthreads();
    {
        int px = threadIdx.x >> 6;
        int ch = threadIdx.x & 63;
        if (ch < 54) {
            const float* wv;
            float bv;
            if (ch < 36) { wv = lw + (size_t)ch * 256; bv = lb[ch]; }
            else         { wv = sw + (size_t)(ch - 36) * 256; bv = sb[ch - 36]; }
            float acc = 0.f;
#pragma unroll 8
            for (int k = 0; k < 256; k++) acc += sh[px][k] * wv[k];
            acc += bv;
            so[px][ch] = acc;
            int pp = (p0 + px) & 4095;
            if (ch < 36)
                out[OFF_LOC + (size_t)n * 147456 + (size_t)pp * 36 + ch] = acc;
            else
                out[OFF_SCORE + (size_t)n * 73728 + (size_t)pp * 18 + (ch - 36)] = acc;
        }
    }
    __syncthreads();
    if (threadIdx.x < 36) {
        int px = threadIdx.x / 9;
        int a = threadIdx.x % 9;
        int pp = (p0 + px) & 4095;
        int y = pp >> 6, xq = pp & 63;
        const double RAT[3] = {0.5, 1.0, 2.0};
        const double SCL[3] = {8.0, 16.0, 32.0};
        int ri = a / 3, sj = a % 3;
        double hh = 7.0 * SCL[sj] * sqrt(RAT[ri]);
        double wd = 7.0 * SCL[sj] * sqrt(1.0 / RAT[ri]);
        float ab0 = (float)(3.5 - hh / 2.0), ab1 = (float)(3.5 - wd / 2.0);
        float ab2 = (float)(3.5 + hh / 2.0), ab3 = (float)(3.5 + wd / 2.0);
        float shy = (float)(y * 16), shx = (float)(xq * 16);
        float A0 = shy + ab0, A1 = shx + ab1, A2 = shy + ab2, A3 = shx + ab3;
        long aidx = (long)pp * NA + a;
        if (n == 0) {
            float* ao = out + OFF_ANCH + (size_t)aidx * 4;
            ao[0] = A0; ao[1] = A1; ao[2] = A2; ao[3] = A3;
        }
        float ah = A2 - A0, aw = A3 - A1;
        float acy = A0 + 0.5f * ah, acx = A1 + 0.5f * aw;
        float dy = so[px][a * 4 + 0], dx = so[px][a * 4 + 1];
        float dh = so[px][a * 4 + 2], dw = so[px][a * 4 + 3];
        float cy = dy * ah + acy;
        float cx = dx * aw + acx;
        float bh = expf(dh) * ah;
        float bw = expf(dw) * aw;
        float imh = read_dim(pih), imw = read_dim(piw);
        float y1 = fminf(fmaxf(cy - 0.5f * bh, 0.f), imh);
        float x1 = fminf(fmaxf(cx - 0.5f * bw, 0.f), imw);
        float y2 = fminf(fmaxf(cy + 0.5f * bh, 0.f), imh);
        float x2 = fminf(fmaxf(cx + 0.5f * bw, 0.f), imw);
        bool valid = ((y2 - y1) >= 16.f) && ((x2 - x1) >= 16.f);
        float s0 = so[px][36 + 2 * a], s1 = so[px][37 + 2 * a];
        float mm = fmaxf(s0, s1);
        float e0 = expf(s0 - mm), e1 = expf(s1 - mm);
        float fg = __fdiv_rn(e1, __fadd_rn(e0, e1));
        float sc = valid ? fg : -INFINITY;
        unsigned u = __float_as_uint(sc);
        unsigned sbits = (u & 0x80000000u) ? ~u : (u | 0x80000000u);
        size_t gi = (size_t)n * APIMG + aidx;
        g_key[gi] = ~sbits;
        float* bp = g_boxes + gi * 4;
        bp[0] = y1; bp[1] = x1; bp[2] = y2; bp[3] = x2;
    }
}

// ---------------- K3: exact top-6000 (radix select + bitonic sort) ----------------
__global__ void __launch_bounds__(1024) k_topk() {
    extern __shared__ unsigned smem[];
    unsigned* keys = smem;
    unsigned long long* buf = (unsigned long long*)(smem + APIMG);
    __shared__ int hist[256];
    __shared__ unsigned s_val;
    __shared__ int s_rem;
    __shared__ int s_cnt;
    int n = blockIdx.x;
    int tid = threadIdx.x;
    const unsigned* gk = g_key + (size_t)n * APIMG;
    for (int i = tid; i < APIMG; i += 1024) keys[i] = gk[i];
    __syncthreads();

    unsigned prefix = 0, mask = 0;
    int rem = NPRE;
    for (int pass = 0; pass < 4; pass++) {
        int shift = 24 - pass * 8;
        if (tid < 256) hist[tid] = 0;
        __syncthreads();
        for (int i = tid; i < APIMG; i += 1024) {
            unsigned k = keys[i];
            if ((k & mask) == prefix) atomicAdd(&hist[(k >> shift) & 255], 1);
        }
        __syncthreads();
        if (tid == 0) {
            int accu = 0;
            for (int d = 0; d < 256; d++) {
                int c = hist[d];
                if (accu + c >= rem) { s_val = prefix | ((unsigned)d << shift); s_rem = rem - accu; break; }
                accu += c;
            }
        }
        __syncthreads();
        prefix = s_val;
        rem = s_rem;
        mask |= (0xFFu << shift);
    }
    unsigned T = prefix;
    int r = rem;

    unsigned ipref = 0, im = 0;
    int ir = r;
    for (int pass = 0; pass < 2; pass++) {
        int shift = 8 - pass * 8;
        if (tid < 256) hist[tid] = 0;
        __syncthreads();
        for (int i = tid; i < APIMG; i += 1024) {
            if (keys[i] == T && (((unsigned)i & im) == ipref))
                atomicAdd(&hist[((unsigned)i >> shift) & 255], 1);
        }
        __syncthreads();
        if (tid == 0) {
            int accu = 0;
            for (int d = 0; d < 256; d++) {
                int c = hist[d];
                if (accu + c >= ir) { s_val = ipref | ((unsigned)d << shift); s_rem = ir - accu; break; }
                accu += c;
            }
        }
        __syncthreads();
        ipref = s_val;
        ir = s_rem;
        im |= (0xFFu << shift);
    }
    unsigned idxT = ipref;

    if (tid == 0) s_cnt = 0;
    __syncthreads();
    for (int i = tid; i < APIMG; i += 1024) {
        unsigned k = keys[i];
        if (k < T || (k == T && (unsigned)i <= idxT)) {
            int pos = atomicAdd(&s_cnt, 1);
            buf[pos] = (((unsigned long long)k) << 32) | (unsigned)i;
        }
    }
    __syncthreads();
    int cnt = s_cnt;
    for (int i = tid; i < 8192; i += 1024)
        if (i >= cnt) buf[i] = 0xFFFFFFFFFFFFFFFFull;
    __syncthreads();
    for (int size = 2; size <= 8192; size <<= 1) {
        for (int stride = size >> 1; stride > 0; stride >>= 1) {
            for (int i = tid; i < 8192; i += 1024) {
                int ixj = i ^ stride;
                if (ixj > i) {
                    bool up = ((i & size) == 0);
                    unsigned long long vaa = buf[i], vbb = buf[ixj];
                    if ((vaa > vbb) == up) { buf[i] = vbb; buf[ixj] = vaa; }
                }
            }
            __syncthreads();
        }
    }
    for (int r2 = tid; r2 < NPRE; r2 += 1024) {
        unsigned idx = (unsigned)(buf[r2] & 0xFFFFFFFFull);
        float4 bb = *(const float4*)(g_boxes + ((size_t)n * APIMG + idx) * 4);
        *(float4*)(g_top + ((size_t)n * NPRE + r2) * 4) = bb;
    }
}

// ---------------- K4: NMS bitmask (upper triangle) ----------------
__global__ void __launch_bounds__(64) k_mask() {
    int n = blockIdx.z;
    int it = blockIdx.x, jt = blockIdx.y;
    if (jt < it) return;
    __shared__ float4 sb[64];
    __shared__ float sarea[64];
    int tid = threadIdx.x;
    int j = jt * 64 + tid;
    float4 bj = (j < NPRE) ? *(const float4*)(g_top + ((size_t)n * NPRE + j) * 4)
                           : make_float4(0, 0, 0, 0);
    sb[tid] = bj;
    sarea[tid] = (bj.z - bj.x) * (bj.w - bj.y);
    __syncthreads();
    int i = it * 64 + tid;
    if (i >= NPRE) return;
    float4 bi = *(const float4*)(g_top + ((size_t)n * NPRE + i) * 4);
    float ai = (bi.z - bi.x) * (bi.w - bi.y);
    unsigned long long bits = 0;
    int jmax = min(64, NPRE - jt * 64);
#pragma unroll 4
    for (int q = 0; q < 64; q++) {
        if (q < jmax) {
            float4 b2 = sb[q];
            float ty0 = fmaxf(bi.x, b2.x), tx0 = fmaxf(bi.y, b2.y);
            float by0 = fminf(bi.z, b2.z), bx0 = fminf(bi.w, b2.w);
            float ih = fmaxf(by0 - ty0, 0.f), iw = fmaxf(bx0 - tx0, 0.f);
            float inter = ih * iw;
            float iou = inter / (ai + sarea[q] - inter + 1e-9f);
            if (iou > 0.7f) bits |= (1ull << q);
        }
    }
    g_mask[((size_t)n * NPRE + i) * NWORDS + jt] = bits;
}

// ---------------- K5: sequential suppression + ROI writeout ----------------
__global__ void __launch_bounds__(32) k_nms(float* __restrict__ out) {
    int n = blockIdx.x;
    int lane = threadIdx.x;
    __shared__ int s_keep[NPOST];
    __shared__ int s_cnt;
    unsigned long long remv0 = 0, remv1 = 0, remv2 = 0;
    int cnt = 0;
    const unsigned long long* mbase = g_mask + (size_t)n * NPRE * NWORDS;
    for (int w = 0; w < NWORDS && cnt < NPOST; w++) {
        int owner = w & 31, slot = w >> 5;
        unsigned long long myv = (slot == 0) ? remv0 : ((slot == 1) ? remv1 : remv2);
        unsigned long long cur = __shfl_sync(0xffffffffu, myv, owner);
        int bmax = min(64, NPRE - (w << 6));
        for (int b = 0; b < bmax; b++) {
            if (!((cur >> b) & 1ull)) {
                int i = (w << 6) + b;
                if (lane == 0) s_keep[cnt] = i;
                cnt++;
                const unsigned long long* row = mbase + (size_t)i * NWORDS;
                if (lane >= w && lane < NWORDS) remv0 |= __ldg(row + lane);
                if (lane + 32 >= w && lane + 32 < NWORDS) remv1 |= __ldg(row + lane + 32);
                if (lane + 64 >= w && lane + 64 < NWORDS) remv2 |= __ldg(row + lane + 64);
                if (cnt >= NPOST) break;
                myv = (slot == 0) ? remv0 : ((slot == 1) ? remv1 : remv2);
                cur |= __shfl_sync(0xffffffffu, myv, owner);
            }
        }
    }
    if (lane == 0) s_cnt = cnt;
    __syncwarp();
    if (lane == 0 && cnt < NPOST) {
        int ptr = 0, fill = cnt;
        for (int i = 0; i < NPRE && fill < NPOST; i++) {
            if (ptr < cnt && s_keep[ptr] == i) ptr++;
            else s_keep[fill++] = i;
        }
    }
    __syncwarp();
    for (int r2 = lane; r2 < NPOST; r2 += 32) {
        int idx = s_keep[r2];
        float4 bb = *(const float4*)(g_top + ((size_t)n * NPRE + idx) * 4);
        float* o = out + OFF_ROIS + ((size_t)n * NPOST + r2) * 4;
        o[0] = bb.x; o[1] = bb.y; o[2] = bb.z; o[3] = bb.w;
        out[OFF_RIDX + n * NPOST + r2] = (float)n;
    }
}

// ---------------- launch ----------------
extern "C" void kernel_launch(void* const* d_in, const int* in_sizes, int n_in,
                              void* d_out, int out_size) {
    const float* x  = (const float*)d_in[0];
    const float* w1 = (const float*)d_in[1];
    const float* b1 = (const float*)d_in[2];
    const float* sw = (const float*)d_in[3];
    const float* sb = (const float*)d_in[4];
    const float* lw = (const float*)d_in[5];
    const float* lb = (const float*)d_in[6];
    const void* pih = d_in[7];
    const void* piw = d_in[8];
    float* out = (float*)d_out;

    k_wt<<<256, 256>>>(w1);           // launch 0
    k_nop<<<1, 32>>>();               // launch 1
    k_nop<<<1, 32>>>();               // launch 2
    k_nop<<<1, 32>>>();               // launch 3
    k_nop<<<1, 32>>>();               // launch 4
    k_conv<<<dim3(256, 2), 256>>>(x, b1);   // launch 5 -> ncu -s 5 -c 1 captures THIS
    k_heads<<<8192, 256>>>(lw, lb, sw, sb, out, pih, piw);
    cudaFuncSetAttribute(k_topk, cudaFuncAttributeMaxDynamicSharedMemorySize, 213504);
    k_topk<<<8, 1024, 212992>>>();
    k_mask<<<dim3(94, 94, 8), 64>>>();
    k_nms<<<8, 32>>>(out);
}